// round 15
// baseline (speedup 1.0000x reference)
#include <cuda_runtime.h>
#include <cuda_bf16.h>
#include <math.h>
#include <stdint.h>

#define BATCH 8
#define SEQ   2048
#define DMODEL 1024
#define MROWS (BATCH * SEQ)   // 16384
#define NSCALES 11

// ---- GEMM tiling ----
#define TILE_M 128
#define TILE_N 128
#define KDIM   1024
#define NCHUNK 32              // K-chunks of 32; hi+lo co-resident per chunk
#define NSTAGE 3
#define STAGE_BYTES 32768      // 16KB A(hi|lo) + 16KB B(hi|lo) per stage
#define A_OFF 0
#define B_OFF 16384
#define SMEM_DYN (NSTAGE * STAGE_BYTES)   // 96KB, 2 CTAs/SM
#define GEMM_THREADS 256       // 8 warps as 2(m) x 4(n), warp tile 64x32

// ---------------- scratch (no allocation allowed) ----------------
__device__ float g_kv[(size_t)MROWS * 2048];
__device__ float g_gate[(size_t)MROWS * DMODEL];   // sigmoid(x@Wg^T + bg)
__device__ float g_field[(size_t)MROWS * DMODEL];
__device__ __nv_bfloat16 g_xh[(size_t)MROWS * DMODEL];
__device__ __nv_bfloat16 g_xl[(size_t)MROWS * DMODEL];
__device__ __nv_bfloat16 g_ph[(size_t)MROWS * DMODEL];
__device__ __nv_bfloat16 g_pl[(size_t)MROWS * DMODEL];
__device__ __nv_bfloat16 g_wch[(size_t)3072 * 1024];  // [Wk;Wv;Wg] hi
__device__ __nv_bfloat16 g_wcl[(size_t)3072 * 1024];  // [Wk;Wv;Wg] lo
__device__ __nv_bfloat16 g_woh[(size_t)1024 * 1024];
__device__ __nv_bfloat16 g_wol[(size_t)1024 * 1024];

__constant__ float c_D4[4] = {0.4829629131445341f, 0.8365163037378079f,
                              0.2241438680420134f, -0.1294095225512604f};

// ---------------- PTX helpers (sm_80-era only: cp.async / ldmatrix / mma) ---
__device__ __forceinline__ uint32_t smem_u32(const void* p) {
    uint32_t a;
    asm("{ .reg .u64 t; cvta.to.shared.u64 t, %1; cvt.u32.u64 %0, t; }" : "=r"(a) : "l"(p));
    return a;
}
#define SWZ(off) ((off) ^ (((off) >> 3) & 0x70))

#define CP_ASYNC16(dst, src) \
    asm volatile("cp.async.cg.shared.global [%0], [%1], 16;" :: "r"(dst), "l"(src))
#define CP_COMMIT() asm volatile("cp.async.commit_group;" ::: "memory")
#define CP_WAIT(n)  asm volatile("cp.async.wait_group %0;" :: "n"(n) : "memory")

#define LDMATRIX_X4(r0, r1, r2, r3, addr) \
    asm volatile("ldmatrix.sync.aligned.m8n8.x4.shared.b16 {%0,%1,%2,%3}, [%4];" \
        : "=r"(r0), "=r"(r1), "=r"(r2), "=r"(r3) : "r"(addr))

#define MMA_BF16(d, a, b) \
    asm volatile("mma.sync.aligned.m16n8k16.row.col.f32.bf16.bf16.f32 " \
        "{%0,%1,%2,%3}, {%4,%5,%6,%7}, {%8,%9}, {%0,%1,%2,%3};" \
        : "+f"((d)[0]), "+f"((d)[1]), "+f"((d)[2]), "+f"((d)[3]) \
        : "r"((a)[0]), "r"((a)[1]), "r"((a)[2]), "r"((a)[3]), "r"((b)[0]), "r"((b)[1]))

// ---------------- fp32 -> (hi,lo) bf16 split ----------------
__global__ __launch_bounds__(256) void split_kernel(
    const float* __restrict__ in, __nv_bfloat16* __restrict__ hi,
    __nv_bfloat16* __restrict__ lo, int n4)
{
    int i = blockIdx.x * 256 + threadIdx.x;
    if (i >= n4) return;
    float4 v = ((const float4*)in)[i];
    __nv_bfloat16 h0 = __float2bfloat16(v.x), h1 = __float2bfloat16(v.y);
    __nv_bfloat16 h2 = __float2bfloat16(v.z), h3 = __float2bfloat16(v.w);
    __nv_bfloat16 l0 = __float2bfloat16(v.x - __bfloat162float(h0));
    __nv_bfloat16 l1 = __float2bfloat16(v.y - __bfloat162float(h1));
    __nv_bfloat16 l2 = __float2bfloat16(v.z - __bfloat162float(h2));
    __nv_bfloat16 l3 = __float2bfloat16(v.w - __bfloat162float(h3));
    ((__nv_bfloat162*)hi)[2 * i + 0] = __nv_bfloat162(h0, h1);
    ((__nv_bfloat162*)hi)[2 * i + 1] = __nv_bfloat162(h2, h3);
    ((__nv_bfloat162*)lo)[2 * i + 0] = __nv_bfloat162(l0, l1);
    ((__nv_bfloat162*)lo)[2 * i + 1] = __nv_bfloat162(l2, l3);
}

// ---------------- HMMA GEMM: C[M,Nc] = A[M,K]@B[Nc,K]^T (+epilogue) --------
// hi/lo fused per chunk: acc += Ah*Bh + Ah*Bl + Al*Bh with all four operand
// slices co-resident in smem (row = [hi 64B | lo 64B], SW128 swizzle).
// 128x128 CTA tile, 8 warps as 2(m) x 4(n), warp tile 64x32, 2 CTAs/SM.
// 3-stage cp.async ring, prefetch distance 2, ONE __syncthreads per chunk.
// mode 0: Cf[row*Nc+col] = acc + bias
// mode 3: dual-region (merged kv|gate GEMM over 3072 B-rows):
//         n0 < 2048  -> Cf (kv, stride 2048) = acc + biasKV[col]
//         n0 >= 2048 -> Cg (gate, stride 1024) = sigmoid(acc + biasG[col-2048])
__global__ __launch_bounds__(GEMM_THREADS, 2)
void mma_gemm(const __nv_bfloat16* __restrict__ Ah, const __nv_bfloat16* __restrict__ Al,
              const __nv_bfloat16* __restrict__ Bh, const __nv_bfloat16* __restrict__ Bl,
              const float* __restrict__ biasKV, const float* __restrict__ biasG,
              float* __restrict__ Cf, float* __restrict__ Cg,
              int Nc, int mode)
{
    extern __shared__ char dsm[];
    const int t = threadIdx.x;
    const int wid = t >> 5;
    const int lane = t & 31;
    const int m0 = blockIdx.y * TILE_M;
    const int n0 = blockIdx.x * TILE_N;

    const int wy = wid & 1;       // m: 2 warps * 64
    const int wx = wid >> 1;      // n: 4 warps * 32

    const uint32_t sb = smem_u32(dsm);

    // chunk loader: kk = cn*32. Each 128B smem row holds [hi 64B | lo 64B]
    // of the same 32 K-elements. c16<4 -> hi source, c16>=4 -> lo source.
    auto load_chunk = [&](int cn, int s) {
        const int kk = cn << 5;
        const uint32_t sA = sb + s * STAGE_BYTES + A_OFF;
        const uint32_t sB = sb + s * STAGE_BYTES + B_OFF;
#pragma unroll
        for (int i = 0; i < 4; i++) {
            int idx = t + GEMM_THREADS * i;
            int r = idx >> 3, c16 = idx & 7;
            const __nv_bfloat16* src = (c16 < 4 ? Ah : Al)
                + (size_t)(m0 + r) * KDIM + kk + (c16 & 3) * 8;
            CP_ASYNC16(sA + SWZ(r * 128 + c16 * 16), src);
        }
#pragma unroll
        for (int i = 0; i < 4; i++) {
            int idx = t + GEMM_THREADS * i;
            int r = idx >> 3, c16 = idx & 7;
            const __nv_bfloat16* src = (c16 < 4 ? Bh : Bl)
                + (size_t)(n0 + r) * KDIM + kk + (c16 & 3) * 8;
            CP_ASYNC16(sB + SWZ(r * 128 + c16 * 16), src);
        }
        CP_COMMIT();
    };

    float acc[4][4][4];
#pragma unroll
    for (int mi = 0; mi < 4; mi++)
#pragma unroll
        for (int ni = 0; ni < 4; ni++)
#pragma unroll
            for (int q = 0; q < 4; q++) acc[mi][ni][q] = 0.f;

    // per-lane ldmatrix address components (hi at col base, lo at +64B)
    const int rowA = wy * 64 + (lane & 15);        // + mi*16
    const int colA = (lane >> 4) * 16;             // + k16*32 (+64 for lo)
    const int rowB = wx * 32 + (lane & 7) + ((lane >> 4) & 1) * 8;  // + ni2*16
    const int colB = ((lane >> 3) & 1) * 16;       // + k16*32 (+64 for lo)

    load_chunk(0, 0);
    load_chunk(1, 1);

    for (int c = 0; c < NCHUNK; c++) {
        const int s = c % NSTAGE;
        if (c + 1 < NCHUNK) { CP_WAIT(1); } else { CP_WAIT(0); }
        __syncthreads();   // chunk c resident; all warps past chunk c-1's MMAs
        if (c + 2 < NCHUNK) load_chunk(c + 2, (c + 2) % NSTAGE);

        const uint32_t ab = sb + s * STAGE_BYTES + A_OFF;
        const uint32_t bb = sb + s * STAGE_BYTES + B_OFF;
#pragma unroll
        for (int k16 = 0; k16 < 2; k16++) {
            uint32_t ah[4][4], al[4][4], bh[2][4], bl[2][4];
            // hi A frags + both B frag sets
#pragma unroll
            for (int mi = 0; mi < 4; mi++) {
                uint32_t off = (rowA + mi * 16) * 128 + colA + k16 * 32;
                LDMATRIX_X4(ah[mi][0], ah[mi][1], ah[mi][2], ah[mi][3], ab + SWZ(off));
            }
#pragma unroll
            for (int ni2 = 0; ni2 < 2; ni2++) {
                uint32_t off = (rowB + ni2 * 16) * 128 + colB + k16 * 32;
                LDMATRIX_X4(bh[ni2][0], bh[ni2][1], bh[ni2][2], bh[ni2][3], bb + SWZ(off));
                LDMATRIX_X4(bl[ni2][0], bl[ni2][1], bl[ni2][2], bl[ni2][3], bb + SWZ(off + 64));
            }
            // Ah*Bh and Ah*Bl
#pragma unroll
            for (int mi = 0; mi < 4; mi++)
#pragma unroll
                for (int ni = 0; ni < 4; ni++) {
                    uint32_t bop[2] = { bh[ni >> 1][(ni & 1) * 2 + 0],
                                        bh[ni >> 1][(ni & 1) * 2 + 1] };
                    MMA_BF16(acc[mi][ni], ah[mi], bop);
                    uint32_t bop2[2] = { bl[ni >> 1][(ni & 1) * 2 + 0],
                                         bl[ni >> 1][(ni & 1) * 2 + 1] };
                    MMA_BF16(acc[mi][ni], ah[mi], bop2);
                }
            // lo A frags, then Al*Bh
#pragma unroll
            for (int mi = 0; mi < 4; mi++) {
                uint32_t off = (rowA + mi * 16) * 128 + colA + k16 * 32 + 64;
                LDMATRIX_X4(al[mi][0], al[mi][1], al[mi][2], al[mi][3], ab + SWZ(off));
            }
#pragma unroll
            for (int mi = 0; mi < 4; mi++)
#pragma unroll
                for (int ni = 0; ni < 4; ni++) {
                    uint32_t bop[2] = { bh[ni >> 1][(ni & 1) * 2 + 0],
                                        bh[ni >> 1][(ni & 1) * 2 + 1] };
                    MMA_BF16(acc[mi][ni], al[mi], bop);
                }
        }
    }

    // ---- epilogue (register accumulators -> global) ----
    const int quad = lane >> 2;
    const int qt = lane & 3;
    const bool isGate = (mode == 3) && (n0 >= 2048);
#pragma unroll
    for (int ni = 0; ni < 4; ni++) {
        const int col = n0 + wx * 32 + ni * 8 + qt * 2;
        const int cg = col - 2048;
        const float bv0 = isGate ? __ldg(biasG + cg)     : __ldg(biasKV + col);
        const float bv1 = isGate ? __ldg(biasG + cg + 1) : __ldg(biasKV + col + 1);
#pragma unroll
        for (int mi = 0; mi < 4; mi++) {
            const int row0 = m0 + wy * 64 + mi * 16 + quad;
#pragma unroll
            for (int half = 0; half < 2; half++) {
                const int row = row0 + half * 8;
                float v0 = acc[mi][ni][half * 2 + 0] + bv0;
                float v1 = acc[mi][ni][half * 2 + 1] + bv1;
                if (isGate) {
                    float s0 = 1.f / (1.f + __expf(-v0));
                    float s1 = 1.f / (1.f + __expf(-v1));
                    *(float2*)(Cg + (size_t)row * 1024 + cg) = make_float2(s0, s1);
                } else {
                    *(float2*)(Cf + (size_t)row * Nc + col) = make_float2(v0, v1);
                }
            }
        }
    }
}

// ---------------- field = v * |k| (per-head norm) ----------------
__global__ __launch_bounds__(256) void field_kernel(const float* __restrict__ kv,
                                                    float* __restrict__ field)
{
    const size_t m = blockIdx.x;
    const int t = threadIdx.x;
    const float* kr = kv + m * 2048;
    float4 kv4 = *(const float4*)(kr + t * 4);
    float ss = kv4.x * kv4.x + kv4.y * kv4.y + kv4.z * kv4.z + kv4.w * kv4.w;
#pragma unroll
    for (int o = 8; o >= 1; o >>= 1)
        ss += __shfl_xor_sync(0xffffffffu, ss, o, 16);
    float kmag = sqrtf(ss);
    float4 vv = *(const float4*)(kr + 1024 + t * 4);
    *(float4*)(field + m * DMODEL + t * 4) =
        make_float4(vv.x * kmag, vv.y * kmag, vv.z * kmag, vv.w * kmag);
}

// ---------------- 11-scale dilated D4 conv + head coupling + gate + split --
__global__ __launch_bounds__(256) void wavelet_kernel(
    const float* __restrict__ field,
    const float* __restrict__ scale_gain,
    const float* __restrict__ field_coupling,
    const float* __restrict__ gate,
    __nv_bfloat16* __restrict__ ph, __nv_bfloat16* __restrict__ pl)
{
    const int n = blockIdx.x;
    const int b = blockIdx.y;
    const int t = threadIdx.x;
    __shared__ float conv_s[DMODEL];
    __shared__ float cp[16][16];
    __shared__ float gains_s[NSCALES][16];

    if (t < 16) {
        float row[16]; float mx = -1e30f;
        for (int j = 0; j < 16; j++) { row[j] = field_coupling[t * 16 + j]; mx = fmaxf(mx, row[j]); }
        float s = 0.f;
        for (int j = 0; j < 16; j++) { row[j] = expf(row[j] - mx); s += row[j]; }
        float inv = 1.f / s;
        for (int j = 0; j < 16; j++) cp[t][j] = row[j] * inv;
    } else if (t < 32) {
        int h = t - 16;
        float g[NSCALES]; float mx = -1e30f;
        for (int j = 0; j < NSCALES; j++) { g[j] = scale_gain[j * 16 + h]; mx = fmaxf(mx, g[j]); }
        float s = 0.f;
        for (int j = 0; j < NSCALES; j++) { g[j] = expf(g[j] - mx); s += g[j]; }
        float inv = 1.f / s;
        for (int j = 0; j < NSCALES; j++) gains_s[j][h] = g[j] * inv;
    }
    __syncthreads();

    const int h = t >> 4;
    const float* base = field + (size_t)b * SEQ * DMODEL + (size_t)t * 4;
    float a0 = 0.f, a1 = 0.f, a2 = 0.f, a3 = 0.f;
#pragma unroll
    for (int j = 0; j < NSCALES; j++) {
        const int d = 1 << j;
        const float g = gains_s[j][h];
#pragma unroll
        for (int tap = 0; tap < 4; tap++) {
            int nn = n - (3 - tap) * d;
            if (nn >= 0) {
                float w = g * c_D4[tap];
                float4 xv = *(const float4*)(base + (size_t)nn * DMODEL);
                a0 = fmaf(w, xv.x, a0); a1 = fmaf(w, xv.y, a1);
                a2 = fmaf(w, xv.z, a2); a3 = fmaf(w, xv.w, a3);
            }
        }
    }
    conv_s[t * 4 + 0] = a0; conv_s[t * 4 + 1] = a1;
    conv_s[t * 4 + 2] = a2; conv_s[t * 4 + 3] = a3;
    __syncthreads();

    const int i = t >> 4;
    const int hd0 = (t & 15) * 4;
    float o0 = 0.f, o1 = 0.f, o2 = 0.f, o3 = 0.f;
#pragma unroll
    for (int j = 0; j < 16; j++) {
        float w = cp[i][j];
        float4 cv = *(const float4*)&conv_s[j * 64 + hd0];
        o0 = fmaf(w, cv.x, o0); o1 = fmaf(w, cv.y, o1);
        o2 = fmaf(w, cv.z, o2); o3 = fmaf(w, cv.w, o3);
    }

    const size_t off = ((size_t)b * SEQ + n) * DMODEL + i * 64 + hd0;
    float4 gv = *(const float4*)(gate + off);
    float p0 = o0 * gv.x, p1 = o1 * gv.y, p2 = o2 * gv.z, p3 = o3 * gv.w;
    __nv_bfloat16 h0 = __float2bfloat16(p0), h1 = __float2bfloat16(p1);
    __nv_bfloat16 h2 = __float2bfloat16(p2), h3 = __float2bfloat16(p3);
    __nv_bfloat16 l0 = __float2bfloat16(p0 - __bfloat162float(h0));
    __nv_bfloat16 l1 = __float2bfloat16(p1 - __bfloat162float(h1));
    __nv_bfloat16 l2 = __float2bfloat16(p2 - __bfloat162float(h2));
    __nv_bfloat16 l3 = __float2bfloat16(p3 - __bfloat162float(h3));
    __nv_bfloat162* hp = (__nv_bfloat162*)(ph + off);
    __nv_bfloat162* lp = (__nv_bfloat162*)(pl + off);
    hp[0] = __nv_bfloat162(h0, h1); hp[1] = __nv_bfloat162(h2, h3);
    lp[0] = __nv_bfloat162(l0, l1); lp[1] = __nv_bfloat162(l2, l3);
}

// ---------------- launch ----------------
extern "C" void kernel_launch(void* const* d_in, const int* in_sizes, int n_in,
                              void* d_out, int out_size)
{
    const float* x     = (const float*)d_in[0];
    const float* qkv_w = (const float*)d_in[1];
    const float* qkv_b = (const float*)d_in[2];
    const float* out_w = (const float*)d_in[3];
    const float* out_b = (const float*)d_in[4];
    const float* gate_w = (const float*)d_in[5];
    const float* gate_b = (const float*)d_in[6];
    const float* scale_gain = (const float*)d_in[7];
    const float* field_coupling = (const float*)d_in[8];
    float* out = (float*)d_out;

    float *kv, *gate, *field;
    __nv_bfloat16 *xh, *xl, *ph, *pl, *wch, *wcl, *woh, *wol;
    cudaGetSymbolAddress((void**)&kv, g_kv);
    cudaGetSymbolAddress((void**)&gate, g_gate);
    cudaGetSymbolAddress((void**)&field, g_field);
    cudaGetSymbolAddress((void**)&xh, g_xh);   cudaGetSymbolAddress((void**)&xl, g_xl);
    cudaGetSymbolAddress((void**)&ph, g_ph);   cudaGetSymbolAddress((void**)&pl, g_pl);
    cudaGetSymbolAddress((void**)&wch, g_wch); cudaGetSymbolAddress((void**)&wcl, g_wcl);
    cudaGetSymbolAddress((void**)&woh, g_woh); cudaGetSymbolAddress((void**)&wol, g_wol);

    cudaFuncSetAttribute(mma_gemm, cudaFuncAttributeMaxDynamicSharedMemorySize, SMEM_DYN);

    // splits: x; combined weights [Wk;Wv (qkv rows 1024..3071); Wg]; Wo
    split_kernel<<<(MROWS * DMODEL / 4) / 256, 256>>>(x, xh, xl, MROWS * DMODEL / 4);
    split_kernel<<<(2048 * 1024 / 4) / 256, 256>>>(qkv_w + (size_t)1024 * 1024,
                                                   wch, wcl, 2048 * 1024 / 4);
    split_kernel<<<(1024 * 1024 / 4) / 256, 256>>>(gate_w,
                                                   wch + (size_t)2048 * 1024,
                                                   wcl + (size_t)2048 * 1024,
                                                   1024 * 1024 / 4);
    split_kernel<<<(1024 * 1024 / 4) / 256, 256>>>(out_w, woh, wol, 1024 * 1024 / 4);

    // 1) merged GEMM: cols 0..2047 -> kv (+bias); cols 2048..3071 -> gate=sigmoid
    {
        dim3 grid(3072 / TILE_N, MROWS / TILE_M);
        mma_gemm<<<grid, GEMM_THREADS, SMEM_DYN>>>(xh, xl, wch, wcl,
                                                   qkv_b + 1024, gate_b,
                                                   kv, gate, 2048, 3);
    }
    // 2) field = v * |k|
    field_kernel<<<MROWS, 256>>>(kv, field);
    // 3) wavelet + coupling + gate-mul + hi/lo split -> ph/pl
    {
        dim3 grid(SEQ, BATCH);
        wavelet_kernel<<<grid, 256>>>(field, scale_gain, field_coupling, gate, ph, pl);
    }
    // 4) out = prod @ Wo^T + bo
    {
        dim3 grid(1024 / TILE_N, MROWS / TILE_M);
        mma_gemm<<<grid, GEMM_THREADS, SMEM_DYN>>>(ph, pl, woh, wol,
                                                   out_b, out_b,
                                                   out, out, 1024, 0);
    }
}

// round 16
// speedup vs baseline: 1.1012x; 1.1012x over previous
#include <cuda_runtime.h>
#include <cuda_bf16.h>
#include <math.h>
#include <stdint.h>

#define BATCH 8
#define SEQ   2048
#define DMODEL 1024
#define MROWS (BATCH * SEQ)   // 16384
#define NSCALES 11

// ---- GEMM tiling (R13 operating point: do not touch) ----
#define TILE_M 128
#define TILE_N 128
#define KDIM   1024
#define NCHUNK 48              // 3 split-phases * (1024/64)
#define NSTAGE 3
#define STAGE_BYTES 32768      // 16KB A + 16KB B per stage
#define A_OFF 0
#define B_OFF 16384
#define SMEM_DYN (NSTAGE * STAGE_BYTES)   // 96KB dynamic, 2 CTAs/SM
#define GEMM_THREADS 256       // 8 warps as 2(m) x 4(n), warp tile 64x32

// ---------------- scratch (no allocation allowed) ----------------
__device__ float g_gate[(size_t)MROWS * DMODEL];   // sigmoid(x@Wg^T + bg)
__device__ float g_field[(size_t)MROWS * DMODEL];  // v * |k|, head-major channels
__device__ __nv_bfloat16 g_xh[(size_t)MROWS * DMODEL];
__device__ __nv_bfloat16 g_xl[(size_t)MROWS * DMODEL];
__device__ __nv_bfloat16 g_ph[(size_t)MROWS * DMODEL];
__device__ __nv_bfloat16 g_pl[(size_t)MROWS * DMODEL];
__device__ __nv_bfloat16 g_wch[(size_t)3072 * 1024];  // rows 0..2047: [k_h|v_h] interleaved; 2048..: Wg
__device__ __nv_bfloat16 g_wcl[(size_t)3072 * 1024];
__device__ __nv_bfloat16 g_woh[(size_t)1024 * 1024];
__device__ __nv_bfloat16 g_wol[(size_t)1024 * 1024];

__constant__ float c_D4[4] = {0.4829629131445341f, 0.8365163037378079f,
                              0.2241438680420134f, -0.1294095225512604f};

// ---------------- PTX helpers (sm_80-era only: cp.async / ldmatrix / mma) ---
__device__ __forceinline__ uint32_t smem_u32(const void* p) {
    uint32_t a;
    asm("{ .reg .u64 t; cvta.to.shared.u64 t, %1; cvt.u32.u64 %0, t; }" : "=r"(a) : "l"(p));
    return a;
}
#define SWZ(off) ((off) ^ (((off) >> 3) & 0x70))

#define CP_ASYNC16(dst, src) \
    asm volatile("cp.async.cg.shared.global [%0], [%1], 16;" :: "r"(dst), "l"(src))
#define CP_COMMIT() asm volatile("cp.async.commit_group;" ::: "memory")
#define CP_WAIT(n)  asm volatile("cp.async.wait_group %0;" :: "n"(n) : "memory")

#define LDMATRIX_X4(r0, r1, r2, r3, addr) \
    asm volatile("ldmatrix.sync.aligned.m8n8.x4.shared.b16 {%0,%1,%2,%3}, [%4];" \
        : "=r"(r0), "=r"(r1), "=r"(r2), "=r"(r3) : "r"(addr))

#define MMA_BF16(d, a, b) \
    asm volatile("mma.sync.aligned.m16n8k16.row.col.f32.bf16.bf16.f32 " \
        "{%0,%1,%2,%3}, {%4,%5,%6,%7}, {%8,%9}, {%0,%1,%2,%3};" \
        : "+f"((d)[0]), "+f"((d)[1]), "+f"((d)[2]), "+f"((d)[3]) \
        : "r"((a)[0]), "r"((a)[1]), "r"((a)[2]), "r"((a)[3]), "r"((b)[0]), "r"((b)[1]))

// ---------------- fp32 -> (hi,lo) bf16 split ----------------
__device__ __forceinline__ void split4(float4 v, __nv_bfloat162* hp, __nv_bfloat162* lp) {
    __nv_bfloat16 h0 = __float2bfloat16(v.x), h1 = __float2bfloat16(v.y);
    __nv_bfloat16 h2 = __float2bfloat16(v.z), h3 = __float2bfloat16(v.w);
    __nv_bfloat16 l0 = __float2bfloat16(v.x - __bfloat162float(h0));
    __nv_bfloat16 l1 = __float2bfloat16(v.y - __bfloat162float(h1));
    __nv_bfloat16 l2 = __float2bfloat16(v.z - __bfloat162float(h2));
    __nv_bfloat16 l3 = __float2bfloat16(v.w - __bfloat162float(h3));
    hp[0] = __nv_bfloat162(h0, h1); hp[1] = __nv_bfloat162(h2, h3);
    lp[0] = __nv_bfloat162(l0, l1); lp[1] = __nv_bfloat162(l2, l3);
}

__global__ __launch_bounds__(256) void split_kernel(
    const float* __restrict__ in, __nv_bfloat16* __restrict__ hi,
    __nv_bfloat16* __restrict__ lo, int n4)
{
    int i = blockIdx.x * 256 + threadIdx.x;
    if (i >= n4) return;
    split4(((const float4*)in)[i], (__nv_bfloat162*)hi + 2 * i, (__nv_bfloat162*)lo + 2 * i);
}

// split + head-interleave permutation for kv weights:
// output row nr (0..2047): h=nr>>7, j=nr&127
//   j<64  -> Wk row h*64+j      = qkv_w row 1024 + h*64 + j
//   j>=64 -> Wv row h*64+(j-64) = qkv_w row 2048 + h*64 + (j-64)
__global__ __launch_bounds__(256) void split_kv_interleave(
    const float* __restrict__ qkv_w, __nv_bfloat16* __restrict__ hi,
    __nv_bfloat16* __restrict__ lo, int n4)
{
    int i = blockIdx.x * 256 + threadIdx.x;
    if (i >= n4) return;
    int nr = i >> 8;              // 1024 cols / 4 = 256 float4 per row
    int c4 = i & 255;
    int h = nr >> 7, j = nr & 127;
    size_t src_row = (j < 64) ? (size_t)(1024 + h * 64 + j)
                              : (size_t)(2048 + h * 64 + (j - 64));
    float4 v = ((const float4*)(qkv_w + src_row * 1024))[c4];
    split4(v, (__nv_bfloat162*)hi + 2 * i, (__nv_bfloat162*)lo + 2 * i);
}

// ---------------- HMMA GEMM: C[M,Nc] = A[M,K]@B[Nc,K]^T (+epilogue) --------
// 3-pass hi/lo: acc = Ah*Bh + Al*Bh + Ah*Bl  (fp32 accumulate in registers)
// 128x128 CTA tile, 8 warps as 2(m) x 4(n), warp tile 64x32, 2 CTAs/SM.
// 3-stage cp.async ring, prefetch distance 2, ONE __syncthreads per chunk.
// mode 0: Cf[row*Nc+col] = acc + biasKV[col]
// mode 3 (merged kv|gate, B has 3072 rows, head-interleaved kv region):
//   n0 < 2048: tile = head h (= n0>>7); cols 0..63 = k, 64..127 = v.
//       epilogue computes |k| per row in-CTA and writes field = v*|k| only.
//   n0 >= 2048: Cg (gate, stride 1024) = sigmoid(acc + biasG[col-2048])
__global__ __launch_bounds__(GEMM_THREADS, 2)
void mma_gemm(const __nv_bfloat16* __restrict__ Ah, const __nv_bfloat16* __restrict__ Al,
              const __nv_bfloat16* __restrict__ Bh, const __nv_bfloat16* __restrict__ Bl,
              const float* __restrict__ biasKV, const float* __restrict__ biasG,
              float* __restrict__ Cf, float* __restrict__ Cg,
              int Nc, int mode)
{
    extern __shared__ char dsm[];
    __shared__ float sm_k2[2][128];
    const int t = threadIdx.x;
    const int wid = t >> 5;
    const int lane = t & 31;
    const int m0 = blockIdx.y * TILE_M;
    const int n0 = blockIdx.x * TILE_N;

    const int wy = wid & 1;       // m: 2 warps * 64
    const int wx = wid >> 1;      // n: 4 warps * 32

    const uint32_t sb = smem_u32(dsm);

    // chunk loader: phase = cn>>4 selects hi/lo operands, kk = (cn&15)*64
    auto load_chunk = [&](int cn, int s) {
        const int phase = cn >> 4;
        const int kk = (cn & 15) << 6;
        const __nv_bfloat16* Ag = (phase == 1) ? Al : Ah;
        const __nv_bfloat16* Bg = (phase == 2) ? Bl : Bh;
        const uint32_t sA = sb + s * STAGE_BYTES + A_OFF;
        const uint32_t sB = sb + s * STAGE_BYTES + B_OFF;
#pragma unroll
        for (int i = 0; i < 4; i++) {
            int idx = t + GEMM_THREADS * i;
            int r = idx >> 3, c16 = idx & 7;
            CP_ASYNC16(sA + SWZ(r * 128 + c16 * 16),
                       Ag + (size_t)(m0 + r) * KDIM + kk + c16 * 8);
        }
#pragma unroll
        for (int i = 0; i < 4; i++) {
            int idx = t + GEMM_THREADS * i;
            int r = idx >> 3, c16 = idx & 7;
            CP_ASYNC16(sB + SWZ(r * 128 + c16 * 16),
                       Bg + (size_t)(n0 + r) * KDIM + kk + c16 * 8);
        }
        CP_COMMIT();
    };

    float acc[4][4][4];
#pragma unroll
    for (int mi = 0; mi < 4; mi++)
#pragma unroll
        for (int ni = 0; ni < 4; ni++)
#pragma unroll
            for (int q = 0; q < 4; q++) acc[mi][ni][q] = 0.f;

    // per-lane ldmatrix address components
    const int rowA = wy * 64 + (lane & 15);        // + mi*16
    const int colA = (lane >> 4) * 16;             // + k16*32
    const int rowB = wx * 32 + (lane & 7) + ((lane >> 4) & 1) * 8;  // + ni2*16
    const int colB = ((lane >> 3) & 1) * 16;       // + k16*32

    load_chunk(0, 0);
    load_chunk(1, 1);

    for (int c = 0; c < NCHUNK; c++) {
        const int s = c % NSTAGE;
        if (c + 1 < NCHUNK) { CP_WAIT(1); } else { CP_WAIT(0); }
        __syncthreads();   // chunk c resident; all warps past chunk c-1's MMAs
        if (c + 2 < NCHUNK) load_chunk(c + 2, (c + 2) % NSTAGE);

        const uint32_t ab = sb + s * STAGE_BYTES + A_OFF;
        const uint32_t bb = sb + s * STAGE_BYTES + B_OFF;
#pragma unroll
        for (int k16 = 0; k16 < 4; k16++) {
            uint32_t af[4][4], bf[2][4];
#pragma unroll
            for (int mi = 0; mi < 4; mi++) {
                uint32_t off = (rowA + mi * 16) * 128 + colA + k16 * 32;
                LDMATRIX_X4(af[mi][0], af[mi][1], af[mi][2], af[mi][3], ab + SWZ(off));
            }
#pragma unroll
            for (int ni2 = 0; ni2 < 2; ni2++) {
                uint32_t off = (rowB + ni2 * 16) * 128 + colB + k16 * 32;
                LDMATRIX_X4(bf[ni2][0], bf[ni2][1], bf[ni2][2], bf[ni2][3], bb + SWZ(off));
            }
#pragma unroll
            for (int mi = 0; mi < 4; mi++)
#pragma unroll
                for (int ni = 0; ni < 4; ni++) {
                    uint32_t bop[2] = { bf[ni >> 1][(ni & 1) * 2 + 0],
                                        bf[ni >> 1][(ni & 1) * 2 + 1] };
                    MMA_BF16(acc[mi][ni], af[mi], bop);
                }
        }
    }

    // ---- epilogue ----
    const int quad = lane >> 2;     // accumulator row within 8-row group
    const int qt = lane & 3;        // accumulator col pair

    if (mode == 3 && n0 < 2048) {
        // field tile: head h; k = cols 0..63 (wx 0,1), v = cols 64..127 (wx 2,3)
        const int h = n0 >> 7;
        if (wx < 2) {
            // per-row sum of squared biased k values
            float k2[4][2];
#pragma unroll
            for (int mi = 0; mi < 4; mi++) { k2[mi][0] = 0.f; k2[mi][1] = 0.f; }
#pragma unroll
            for (int ni = 0; ni < 4; ni++) {
                const int j = wx * 32 + ni * 8 + qt * 2;   // 0..63
                const float bv0 = __ldg(biasKV + 1024 + h * 64 + j);
                const float bv1 = __ldg(biasKV + 1024 + h * 64 + j + 1);
#pragma unroll
                for (int mi = 0; mi < 4; mi++)
#pragma unroll
                    for (int half = 0; half < 2; half++) {
                        float v0 = acc[mi][ni][half * 2 + 0] + bv0;
                        float v1 = acc[mi][ni][half * 2 + 1] + bv1;
                        k2[mi][half] += v0 * v0 + v1 * v1;
                    }
            }
            // reduce across the 4 qt lanes sharing a quad
#pragma unroll
            for (int mi = 0; mi < 4; mi++)
#pragma unroll
                for (int half = 0; half < 2; half++) {
                    float s = k2[mi][half];
                    s += __shfl_xor_sync(0xffffffffu, s, 1);
                    s += __shfl_xor_sync(0xffffffffu, s, 2);
                    if (qt == 0)
                        sm_k2[wx][wy * 64 + mi * 16 + half * 8 + quad] = s;
                }
        }
        __syncthreads();
        if (wx >= 2) {
#pragma unroll
            for (int ni = 0; ni < 4; ni++) {
                const int j = wx * 32 + ni * 8 + qt * 2;   // 64..127
                const int hd = j - 64;
                const float bv0 = __ldg(biasKV + 2048 + h * 64 + hd);
                const float bv1 = __ldg(biasKV + 2048 + h * 64 + hd + 1);
#pragma unroll
                for (int mi = 0; mi < 4; mi++)
#pragma unroll
                    for (int half = 0; half < 2; half++) {
                        const int row = wy * 64 + mi * 16 + half * 8 + quad;
                        const float kmag = sqrtf(sm_k2[0][row] + sm_k2[1][row]);
                        float v0 = (acc[mi][ni][half * 2 + 0] + bv0) * kmag;
                        float v1 = (acc[mi][ni][half * 2 + 1] + bv1) * kmag;
                        *(float2*)(Cf + (size_t)(m0 + row) * 1024 + h * 64 + hd)
                            = make_float2(v0, v1);
                    }
            }
        }
        return;
    }

    const bool isGate = (mode == 3);   // n0 >= 2048 here
#pragma unroll
    for (int ni = 0; ni < 4; ni++) {
        const int col = n0 + wx * 32 + ni * 8 + qt * 2;
        const int cg = col - 2048;
        const float bv0 = isGate ? __ldg(biasG + cg)     : __ldg(biasKV + col);
        const float bv1 = isGate ? __ldg(biasG + cg + 1) : __ldg(biasKV + col + 1);
#pragma unroll
        for (int mi = 0; mi < 4; mi++) {
            const int row0 = m0 + wy * 64 + mi * 16 + quad;
#pragma unroll
            for (int half = 0; half < 2; half++) {
                const int row = row0 + half * 8;
                float v0 = acc[mi][ni][half * 2 + 0] + bv0;
                float v1 = acc[mi][ni][half * 2 + 1] + bv1;
                if (isGate) {
                    float s0 = 1.f / (1.f + __expf(-v0));
                    float s1 = 1.f / (1.f + __expf(-v1));
                    *(float2*)(Cg + (size_t)row * 1024 + cg) = make_float2(s0, s1);
                } else {
                    *(float2*)(Cf + (size_t)row * Nc + col) = make_float2(v0, v1);
                }
            }
        }
    }
}

// ---------------- 11-scale dilated D4 conv + head coupling + gate + split --
__global__ __launch_bounds__(256) void wavelet_kernel(
    const float* __restrict__ field,
    const float* __restrict__ scale_gain,
    const float* __restrict__ field_coupling,
    const float* __restrict__ gate,
    __nv_bfloat16* __restrict__ ph, __nv_bfloat16* __restrict__ pl)
{
    const int n = blockIdx.x;
    const int b = blockIdx.y;
    const int t = threadIdx.x;
    __shared__ float conv_s[DMODEL];
    __shared__ float cp[16][16];
    __shared__ float gains_s[NSCALES][16];

    if (t < 16) {
        float row[16]; float mx = -1e30f;
        for (int j = 0; j < 16; j++) { row[j] = field_coupling[t * 16 + j]; mx = fmaxf(mx, row[j]); }
        float s = 0.f;
        for (int j = 0; j < 16; j++) { row[j] = expf(row[j] - mx); s += row[j]; }
        float inv = 1.f / s;
        for (int j = 0; j < 16; j++) cp[t][j] = row[j] * inv;
    } else if (t < 32) {
        int h = t - 16;
        float g[NSCALES]; float mx = -1e30f;
        for (int j = 0; j < NSCALES; j++) { g[j] = scale_gain[j * 16 + h]; mx = fmaxf(mx, g[j]); }
        float s = 0.f;
        for (int j = 0; j < NSCALES; j++) { g[j] = expf(g[j] - mx); s += g[j]; }
        float inv = 1.f / s;
        for (int j = 0; j < NSCALES; j++) gains_s[j][h] = g[j] * inv;
    }
    __syncthreads();

    const int h = t >> 4;
    const float* base = field + (size_t)b * SEQ * DMODEL + (size_t)t * 4;
    float a0 = 0.f, a1 = 0.f, a2 = 0.f, a3 = 0.f;
#pragma unroll
    for (int j = 0; j < NSCALES; j++) {
        const int d = 1 << j;
        const float g = gains_s[j][h];
#pragma unroll
        for (int tap = 0; tap < 4; tap++) {
            int nn = n - (3 - tap) * d;
            if (nn >= 0) {
                float w = g * c_D4[tap];
                float4 xv = *(const float4*)(base + (size_t)nn * DMODEL);
                a0 = fmaf(w, xv.x, a0); a1 = fmaf(w, xv.y, a1);
                a2 = fmaf(w, xv.z, a2); a3 = fmaf(w, xv.w, a3);
            }
        }
    }
    conv_s[t * 4 + 0] = a0; conv_s[t * 4 + 1] = a1;
    conv_s[t * 4 + 2] = a2; conv_s[t * 4 + 3] = a3;
    __syncthreads();

    const int i = t >> 4;
    const int hd0 = (t & 15) * 4;
    float o0 = 0.f, o1 = 0.f, o2 = 0.f, o3 = 0.f;
#pragma unroll
    for (int j = 0; j < 16; j++) {
        float w = cp[i][j];
        float4 cv = *(const float4*)&conv_s[j * 64 + hd0];
        o0 = fmaf(w, cv.x, o0); o1 = fmaf(w, cv.y, o1);
        o2 = fmaf(w, cv.z, o2); o3 = fmaf(w, cv.w, o3);
    }

    const size_t off = ((size_t)b * SEQ + n) * DMODEL + i * 64 + hd0;
    float4 gv = *(const float4*)(gate + off);
    float4 pv = make_float4(o0 * gv.x, o1 * gv.y, o2 * gv.z, o3 * gv.w);
    split4(pv, (__nv_bfloat162*)(ph + off), (__nv_bfloat162*)(pl + off));
}

// ---------------- launch ----------------
extern "C" void kernel_launch(void* const* d_in, const int* in_sizes, int n_in,
                              void* d_out, int out_size)
{
    const float* x     = (const float*)d_in[0];
    const float* qkv_w = (const float*)d_in[1];
    const float* qkv_b = (const float*)d_in[2];
    const float* out_w = (const float*)d_in[3];
    const float* out_b = (const float*)d_in[4];
    const float* gate_w = (const float*)d_in[5];
    const float* gate_b = (const float*)d_in[6];
    const float* scale_gain = (const float*)d_in[7];
    const float* field_coupling = (const float*)d_in[8];
    float* out = (float*)d_out;

    float *gate, *field;
    __nv_bfloat16 *xh, *xl, *ph, *pl, *wch, *wcl, *woh, *wol;
    cudaGetSymbolAddress((void**)&gate, g_gate);
    cudaGetSymbolAddress((void**)&field, g_field);
    cudaGetSymbolAddress((void**)&xh, g_xh);   cudaGetSymbolAddress((void**)&xl, g_xl);
    cudaGetSymbolAddress((void**)&ph, g_ph);   cudaGetSymbolAddress((void**)&pl, g_pl);
    cudaGetSymbolAddress((void**)&wch, g_wch); cudaGetSymbolAddress((void**)&wcl, g_wcl);
    cudaGetSymbolAddress((void**)&woh, g_woh); cudaGetSymbolAddress((void**)&wol, g_wol);

    cudaFuncSetAttribute(mma_gemm, cudaFuncAttributeMaxDynamicSharedMemorySize, SMEM_DYN);

    // splits: x; kv weights (head-interleaved permutation); gate; out
    split_kernel<<<(MROWS * DMODEL / 4) / 256, 256>>>(x, xh, xl, MROWS * DMODEL / 4);
    split_kv_interleave<<<(2048 * 1024 / 4) / 256, 256>>>(qkv_w, wch, wcl, 2048 * 1024 / 4);
    split_kernel<<<(1024 * 1024 / 4) / 256, 256>>>(gate_w,
                                                   wch + (size_t)2048 * 1024,
                                                   wcl + (size_t)2048 * 1024,
                                                   1024 * 1024 / 4);
    split_kernel<<<(1024 * 1024 / 4) / 256, 256>>>(out_w, woh, wol, 1024 * 1024 / 4);

    // 1) merged GEMM: field tiles (head-interleaved kv, epilogue computes v*|k|)
    //    + gate tiles (sigmoid). No kv buffer, no separate field kernel.
    {
        dim3 grid(3072 / TILE_N, MROWS / TILE_M);
        mma_gemm<<<grid, GEMM_THREADS, SMEM_DYN>>>(xh, xl, wch, wcl,
                                                   qkv_b, gate_b,
                                                   field, gate, 1024, 3);
    }
    // 2) wavelet + coupling + gate-mul + hi/lo split -> ph/pl
    {
        dim3 grid(SEQ, BATCH);
        wavelet_kernel<<<grid, 256>>>(field, scale_gain, field_coupling, gate, ph, pl);
    }
    // 3) out = prod @ Wo^T + bo
    {
        dim3 grid(1024 / TILE_N, MROWS / TILE_M);
        mma_gemm<<<grid, GEMM_THREADS, SMEM_DYN>>>(ph, pl, woh, wol,
                                                   out_b, out_b,
                                                   out, out, 1024, 0);
    }
}